// round 2
// baseline (speedup 1.0000x reference)
#include <cuda_runtime.h>
#include <cstdint>
#include <cstddef>

#define T_STEPS 512
#define BATCH   32
#define HID     1024
#define GDIM    4096
#define MROWS   16384          // T*B
#define YW      2048           // 2*H
#define NCTA_REC 128
#define REC_SMEM (HID*BATCH*4 + 64*33*4)   // 131072 + 8448 = 139520 B

// ---------------- device scratch (no runtime allocation) ----------------
__device__ float g_gx[134217728];     // [2][MROWS][GDIM]  512 MB
__device__ float g_ybuf[67108864];    // [2][MROWS][YW]    256 MB
__device__ float g_hT[2][2][HID*BATCH];  // [dir][parity][u*32+b]
__device__ unsigned g_bar_cnt   = 0;
__device__ unsigned g_bar_phase = 0;

// ---------------- helpers ----------------
__device__ __forceinline__ float hsig(float v)  { return fminf(fmaxf(fmaf(v, 0.2f, 0.5f), 0.0f), 1.0f); }
__device__ __forceinline__ float clip1(float v) { return fminf(fmaxf(v, -1.0f), 1.0f); }

// sense-reversing grid barrier across NCTA_REC co-resident CTAs
__device__ __forceinline__ void grid_barrier(unsigned& sense) {
    __syncthreads();
    __threadfence();
    sense ^= 1u;
    if (threadIdx.x == 0) {
        if (atomicAdd(&g_bar_cnt, 1u) == NCTA_REC - 1u) {
            atomicExch(&g_bar_cnt, 0u);
            __threadfence();
            atomicExch(&g_bar_phase, sense);
        } else {
            while (atomicAdd(&g_bar_phase, 0u) != sense) { __nanosleep(64); }
        }
    }
    __syncthreads();
    __threadfence();
}

// ---------------- input-projection GEMM ----------------
// G[z][m][n] = sum_k A[m][k] * W_z[n][k] + b1_z[n] + b2_z[n]
// 128x128 tile, 256 threads, 8x8 per thread, K-tile 8, register prefetch.
__global__ void __launch_bounds__(256)
gemm_bias(const float* __restrict__ A, int K, float* __restrict__ G,
          const float* __restrict__ Wf, const float* __restrict__ bf1, const float* __restrict__ bf2,
          const float* __restrict__ Wr, const float* __restrict__ br1, const float* __restrict__ br2)
{
    const int z = blockIdx.z;
    const float* __restrict__ W  = z ? Wr  : Wf;
    const float* __restrict__ b1 = z ? br1 : bf1;
    const float* __restrict__ b2 = z ? br2 : bf2;
    float* __restrict__ Gz = G + (size_t)z * MROWS * GDIM;

    const int n0 = blockIdx.x * 128;
    const int m0 = blockIdx.y * 128;

    __shared__ __align__(16) float As[8][128];
    __shared__ __align__(16) float Bs[8][128];

    const int t  = threadIdx.x;
    const int lr = t >> 1;           // 0..127: tile row loaded by this thread
    const int lq = (t & 1) * 4;      // k-quad 0 or 4
    const int tx = t & 15;           // n microtile
    const int ty = t >> 4;           // m microtile

    float acc[8][8];
#pragma unroll
    for (int i = 0; i < 8; i++)
#pragma unroll
        for (int j = 0; j < 8; j++) acc[i][j] = 0.0f;

    const int nk = K >> 3;
    const float* Ap = A + (size_t)(m0 + lr) * K + lq;
    const float* Wp = W + (size_t)(n0 + lr) * K + lq;
    float4 av = *(const float4*)Ap;
    float4 bv = *(const float4*)Wp;

    for (int kt = 0; kt < nk; kt++) {
        __syncthreads();
        As[lq + 0][lr] = av.x; As[lq + 1][lr] = av.y;
        As[lq + 2][lr] = av.z; As[lq + 3][lr] = av.w;
        Bs[lq + 0][lr] = bv.x; Bs[lq + 1][lr] = bv.y;
        Bs[lq + 2][lr] = bv.z; Bs[lq + 3][lr] = bv.w;
        __syncthreads();
        if (kt + 1 < nk) {
            av = *(const float4*)(Ap + (kt + 1) * 8);
            bv = *(const float4*)(Wp + (kt + 1) * 8);
        }
#pragma unroll
        for (int k = 0; k < 8; k++) {
            float4 a0 = *(const float4*)&As[k][ty * 8];
            float4 a1 = *(const float4*)&As[k][ty * 8 + 4];
            float4 c0 = *(const float4*)&Bs[k][tx * 8];
            float4 c1 = *(const float4*)&Bs[k][tx * 8 + 4];
            float ar[8] = {a0.x, a0.y, a0.z, a0.w, a1.x, a1.y, a1.z, a1.w};
            float cr[8] = {c0.x, c0.y, c0.z, c0.w, c1.x, c1.y, c1.z, c1.w};
#pragma unroll
            for (int i = 0; i < 8; i++)
#pragma unroll
                for (int j = 0; j < 8; j++)
                    acc[i][j] = fmaf(ar[i], cr[j], acc[i][j]);
        }
    }

    float bs[8];
#pragma unroll
    for (int j = 0; j < 8; j++) {
        int n = n0 + tx * 8 + j;
        bs[j] = b1[n] + b2[n];
    }
#pragma unroll
    for (int i = 0; i < 8; i++) {
        float* out = Gz + (size_t)(m0 + ty * 8 + i) * GDIM + n0 + tx * 8;
        float4 o0 = make_float4(acc[i][0] + bs[0], acc[i][1] + bs[1],
                                acc[i][2] + bs[2], acc[i][3] + bs[3]);
        float4 o1 = make_float4(acc[i][4] + bs[4], acc[i][5] + bs[5],
                                acc[i][6] + bs[6], acc[i][7] + bs[7]);
        *(float4*)out       = o0;
        *(float4*)(out + 4) = o1;
    }
}

// ---------------- persistent bidirectional recurrence ----------------
// 128 CTAs: dir = blockIdx.x>>6, 64 CTAs per dir, each owns 16 hidden units.
// Thread (rr = tid&63, bg = tid>>6): gate row rr (4 gates x 16 units), 8 batches.
__global__ void __launch_bounds__(256)
rec_kernel(const float* __restrict__ whhF, const float* __restrict__ whhR,
           const float* __restrict__ h0,  const float* __restrict__ c0,
           int layer, const float* __restrict__ gx, float* __restrict__ yout)
{
    extern __shared__ float smem[];
    float* hs   = smem;                 // [1024][32]
    float* gbuf = smem + HID * BATCH;   // [64][33] padded

    const int tid = threadIdx.x;
    const int dir = blockIdx.x >> 6;
    const int cb  = blockIdx.x & 63;
    const float* __restrict__ whh = dir ? whhR : whhF;
    const float* __restrict__ gxd = gx + (size_t)dir * MROWS * GDIM;

    const int rr   = tid & 63;
    const int bg   = tid >> 6;
    const int b0   = bg * 8;
    const int gate = rr >> 4;
    const int ul   = rr & 15;
    const int row  = gate * HID + cb * 16 + ul;

    // gate-combine ownership: 2 (unit,batch) pairs per thread
    int ug[2], bq[2], ulq[2];
    float cst[2];
#pragma unroll
    for (int q = 0; q < 2; q++) {
        int p   = tid * 2 + q;
        ulq[q]  = p >> 5;
        bq[q]   = p & 31;
        ug[q]   = cb * 16 + ulq[q];
        size_t sidx = (size_t)(2 * layer + dir) * BATCH * HID + (size_t)bq[q] * HID + ug[q];
        cst[q] = c0[sidx];
        __stcg(&g_hT[dir][0][ug[q] * BATCH + bq[q]], h0[sidx]);
    }

    unsigned sense = 0;
    grid_barrier(sense);   // publish initial h

    for (int t = 0; t < T_STEPS; t++) {
        const int par = t & 1;
        const int te  = dir ? (T_STEPS - 1 - t) : t;

        // stage h (128 KB) into smem, bypassing L1
        {
            const float4* s4 = (const float4*)g_hT[dir][par];
            float4* d4 = (float4*)hs;
            for (int i = tid; i < HID * BATCH / 4; i += 256)
                d4[i] = __ldcg(s4 + i);
        }
        __syncthreads();

        // g[b][row] = gx[te][b][row] + sum_k h[b][k] * w_hh[row][k]
        float a0 = 0.f, a1 = 0.f, a2 = 0.f, a3 = 0.f,
              a4 = 0.f, a5 = 0.f, a6 = 0.f, a7 = 0.f;
        const float4* wp = (const float4*)(whh + (size_t)row * HID);
#pragma unroll 4
        for (int k4 = 0; k4 < HID / 4; k4++) {
            float4 w = wp[k4];
            const float* hb = hs + k4 * 4 * BATCH + b0;
            float4 ha, hc;
#define KSTEP(WW, OFF)                                                  \
            ha = *(const float4*)(hb + (OFF));                          \
            hc = *(const float4*)(hb + (OFF) + 4);                      \
            a0 = fmaf(WW, ha.x, a0); a1 = fmaf(WW, ha.y, a1);           \
            a2 = fmaf(WW, ha.z, a2); a3 = fmaf(WW, ha.w, a3);           \
            a4 = fmaf(WW, hc.x, a4); a5 = fmaf(WW, hc.y, a5);           \
            a6 = fmaf(WW, hc.z, a6); a7 = fmaf(WW, hc.w, a7);
            KSTEP(w.x, 0)
            KSTEP(w.y, 32)
            KSTEP(w.z, 64)
            KSTEP(w.w, 96)
#undef KSTEP
        }
        {
            const float* gxrow = gxd + (size_t)(te * BATCH) * GDIM + row;
            float* gb_ = gbuf + rr * 33 + b0;
            gb_[0] = a0 + __ldcs(gxrow + (size_t)(b0 + 0) * GDIM);
            gb_[1] = a1 + __ldcs(gxrow + (size_t)(b0 + 1) * GDIM);
            gb_[2] = a2 + __ldcs(gxrow + (size_t)(b0 + 2) * GDIM);
            gb_[3] = a3 + __ldcs(gxrow + (size_t)(b0 + 3) * GDIM);
            gb_[4] = a4 + __ldcs(gxrow + (size_t)(b0 + 4) * GDIM);
            gb_[5] = a5 + __ldcs(gxrow + (size_t)(b0 + 5) * GDIM);
            gb_[6] = a6 + __ldcs(gxrow + (size_t)(b0 + 6) * GDIM);
            gb_[7] = a7 + __ldcs(gxrow + (size_t)(b0 + 7) * GDIM);
        }
        __syncthreads();

        // gate combine + state update + outputs
#pragma unroll
        for (int q = 0; q < 2; q++) {
            int u = ulq[q], b = bq[q];
            float iv = hsig (gbuf[( 0 + u) * 33 + b]);
            float fv = hsig (gbuf[(16 + u) * 33 + b]);
            float gv = clip1(gbuf[(32 + u) * 33 + b]);
            float ov = hsig (gbuf[(48 + u) * 33 + b]);
            float c  = fv * cst[q] + iv * gv;
            cst[q]   = c;
            float h  = ov * clip1(c);
            __stcg(&g_hT[dir][par ^ 1][ug[q] * BATCH + b], h);
            yout[(size_t)te * BATCH * YW + (size_t)b * YW + dir * HID + ug[q]] = h;
        }

        if (t < T_STEPS - 1) grid_barrier(sense);
    }
}

// ---------------- launch ----------------
extern "C" void kernel_launch(void* const* d_in, const int* in_sizes, int n_in,
                              void* d_out, int out_size)
{
    (void)in_sizes; (void)n_in; (void)out_size;

    const float* x  = (const float*)d_in[0];
    const float* h0 = (const float*)d_in[1];
    const float* c0 = (const float*)d_in[2];
    const float* P[24];
    for (int i = 0; i < 24; i++) P[i] = (const float*)d_in[3 + i];
    // P[(l*2+d)*4 + {0:w_ih, 1:w_hh, 2:b_ih, 3:b_hh}]

    float *gx = nullptr, *yb = nullptr;
    cudaGetSymbolAddress((void**)&gx, g_gx);
    cudaGetSymbolAddress((void**)&yb, g_ybuf);
    cudaFuncSetAttribute(rec_kernel, cudaFuncAttributeMaxDynamicSharedMemorySize, REC_SMEM);

    float* y0  = yb;
    float* y1  = yb + (size_t)MROWS * YW;
    float* out = (float*)d_out;

    dim3 gb(256), gg(GDIM / 128, MROWS / 128, 2);

    // layer 0  (K = 320)
    gemm_bias<<<gg, gb>>>(x, 320, gx, P[0], P[2], P[3], P[4], P[6], P[7]);
    rec_kernel<<<NCTA_REC, 256, REC_SMEM>>>(P[1], P[5], h0, c0, 0, gx, y0);

    // layer 1  (K = 2048)
    gemm_bias<<<gg, gb>>>(y0, 2048, gx, P[8], P[10], P[11], P[12], P[14], P[15]);
    rec_kernel<<<NCTA_REC, 256, REC_SMEM>>>(P[9], P[13], h0, c0, 1, gx, y1);

    // layer 2  (K = 2048)
    gemm_bias<<<gg, gb>>>(y1, 2048, gx, P[16], P[18], P[19], P[20], P[22], P[23]);
    rec_kernel<<<NCTA_REC, 256, REC_SMEM>>>(P[17], P[21], h0, c0, 2, gx, out);
}

// round 3
// speedup vs baseline: 1.0464x; 1.0464x over previous
#include <cuda_runtime.h>
#include <cstdint>
#include <cstddef>

#define T_STEPS 512
#define BATCH   32
#define HID     1024
#define GDIM    4096
#define MROWS   16384          // T*B
#define YW      2048           // 2*H
#define REC_SMEM (HID*BATCH*4 + 64*33*4)   // 131072 + 8448 = 139520 B

typedef unsigned long long ull;

// ---------------- device scratch (no runtime allocation) ----------------
__device__ float g_gx[134217728];        // [2][MROWS][GDIM]  512 MB
__device__ float g_ybuf[67108864];       // [2][MROWS][YW]    256 MB
__device__ float g_hT[2][2][HID*BATCH];  // [dir][parity][u*32+b]
__device__ unsigned g_bar_cnt[2]   = {0, 0};
__device__ unsigned g_bar_phase[2] = {0, 0};

// ---------------- packed fp32 helpers (Blackwell FFMA2) ----------------
__device__ __forceinline__ ull ffma2(ull a, ull b, ull c) {
    ull d;
    asm("fma.rn.f32x2 %0, %1, %2, %3;" : "=l"(d) : "l"(a), "l"(b), "l"(c));
    return d;
}
__device__ __forceinline__ ull pack2(float x, float y) {
    ull r;
    asm("mov.b64 %0, {%1, %2};" : "=l"(r) : "f"(x), "f"(y));
    return r;
}
__device__ __forceinline__ float2 unpack2(ull v) {
    float2 r;
    asm("mov.b64 {%0, %1}, %2;" : "=f"(r.x), "=f"(r.y) : "l"(v));
    return r;
}

__device__ __forceinline__ float hsig(float v)  { return fminf(fmaxf(fmaf(v, 0.2f, 0.5f), 0.0f), 1.0f); }
__device__ __forceinline__ float clip1(float v) { return fminf(fmaxf(v, -1.0f), 1.0f); }

// sense-reversing grid barrier across the 64 CTAs of one direction
__device__ __forceinline__ void grid_barrier(int dir, unsigned& sense) {
    __syncthreads();
    __threadfence();
    sense ^= 1u;
    if (threadIdx.x == 0) {
        if (atomicAdd(&g_bar_cnt[dir], 1u) == 63u) {
            atomicExch(&g_bar_cnt[dir], 0u);
            __threadfence();
            atomicExch(&g_bar_phase[dir], sense);
        } else {
            while (atomicAdd(&g_bar_phase[dir], 0u) != sense) { __nanosleep(64); }
        }
    }
    __syncthreads();
    __threadfence();
}

// ---------------- input-projection GEMM (FFMA2 inner) ----------------
// G[z][m][n] = sum_k A[m][k] * W_z[n][k] + b1_z[n] + b2_z[n]
// 128x128 tile, 256 threads, 8x8 per thread (acc as 8x4 f32x2 pairs), K-tile 8.
__global__ void __launch_bounds__(256)
gemm_bias(const float* __restrict__ A, int K, float* __restrict__ G,
          const float* __restrict__ Wf, const float* __restrict__ bf1, const float* __restrict__ bf2,
          const float* __restrict__ Wr, const float* __restrict__ br1, const float* __restrict__ br2)
{
    const int z = blockIdx.z;
    const float* __restrict__ W  = z ? Wr  : Wf;
    const float* __restrict__ b1 = z ? br1 : bf1;
    const float* __restrict__ b2 = z ? br2 : bf2;
    float* __restrict__ Gz = G + (size_t)z * MROWS * GDIM;

    const int n0 = blockIdx.x * 128;
    const int m0 = blockIdx.y * 128;

    __shared__ __align__(16) float As[8][128];
    __shared__ __align__(16) float Bs[8][128];

    const int t  = threadIdx.x;
    const int lr = t >> 1;           // 0..127: tile row loaded by this thread
    const int lq = (t & 1) * 4;      // k-quad 0 or 4
    const int tx = t & 15;           // n microtile
    const int ty = t >> 4;           // m microtile

    ull acc2[8][4];
#pragma unroll
    for (int i = 0; i < 8; i++)
#pragma unroll
        for (int j = 0; j < 4; j++) acc2[i][j] = 0ULL;

    const int nk = K >> 3;
    const float* Ap = A + (size_t)(m0 + lr) * K + lq;
    const float* Wp = W + (size_t)(n0 + lr) * K + lq;
    float4 av = *(const float4*)Ap;
    float4 bv = *(const float4*)Wp;

    for (int kt = 0; kt < nk; kt++) {
        __syncthreads();
        As[lq + 0][lr] = av.x; As[lq + 1][lr] = av.y;
        As[lq + 2][lr] = av.z; As[lq + 3][lr] = av.w;
        Bs[lq + 0][lr] = bv.x; Bs[lq + 1][lr] = bv.y;
        Bs[lq + 2][lr] = bv.z; Bs[lq + 3][lr] = bv.w;
        __syncthreads();
        if (kt + 1 < nk) {
            av = *(const float4*)(Ap + (kt + 1) * 8);
            bv = *(const float4*)(Wp + (kt + 1) * 8);
        }
#pragma unroll
        for (int k = 0; k < 8; k++) {
            float4 a0 = *(const float4*)&As[k][ty * 8];
            float4 a1 = *(const float4*)&As[k][ty * 8 + 4];
            ulonglong2 cA = *(const ulonglong2*)&Bs[k][tx * 8];
            ulonglong2 cB = *(const ulonglong2*)&Bs[k][tx * 8 + 4];
            ull ai;
#define GROW(i, AV)                                         \
            ai = pack2(AV, AV);                             \
            acc2[i][0] = ffma2(ai, cA.x, acc2[i][0]);       \
            acc2[i][1] = ffma2(ai, cA.y, acc2[i][1]);       \
            acc2[i][2] = ffma2(ai, cB.x, acc2[i][2]);       \
            acc2[i][3] = ffma2(ai, cB.y, acc2[i][3]);
            GROW(0, a0.x) GROW(1, a0.y) GROW(2, a0.z) GROW(3, a0.w)
            GROW(4, a1.x) GROW(5, a1.y) GROW(6, a1.z) GROW(7, a1.w)
#undef GROW
        }
    }

    float bs[8];
#pragma unroll
    for (int j = 0; j < 8; j++) {
        int n = n0 + tx * 8 + j;
        bs[j] = b1[n] + b2[n];
    }
#pragma unroll
    for (int i = 0; i < 8; i++) {
        float2 p0 = unpack2(acc2[i][0]);
        float2 p1 = unpack2(acc2[i][1]);
        float2 p2 = unpack2(acc2[i][2]);
        float2 p3 = unpack2(acc2[i][3]);
        float* out = Gz + (size_t)(m0 + ty * 8 + i) * GDIM + n0 + tx * 8;
        float4 o0 = make_float4(p0.x + bs[0], p0.y + bs[1], p1.x + bs[2], p1.y + bs[3]);
        float4 o1 = make_float4(p2.x + bs[4], p2.y + bs[5], p3.x + bs[6], p3.y + bs[7]);
        *(float4*)out       = o0;
        *(float4*)(out + 4) = o1;
    }
}

// ---------------- persistent bidirectional recurrence ----------------
// 128 CTAs x 128 threads. dir = blockIdx.x>>6; CTA owns 16 units (64 gate rows).
// Thread: 2 gate rows x 8 batches; FFMA2 over batch pairs, w broadcast-packed.
__global__ void __launch_bounds__(128)
rec_kernel(const float* __restrict__ whhF, const float* __restrict__ whhR,
           const float* __restrict__ h0,  const float* __restrict__ c0,
           int layer, const float* __restrict__ gx, float* __restrict__ yout)
{
    extern __shared__ float smem[];
    float* hs   = smem;                 // [1024][32]
    float* gbuf = smem + HID * BATCH;   // [64][33] padded

    const int tid = threadIdx.x;
    const int dir = blockIdx.x >> 6;
    const int cb  = blockIdx.x & 63;
    const float* __restrict__ whh = dir ? whhR : whhF;
    const float* __restrict__ gxd = gx + (size_t)dir * MROWS * GDIM;

    const int rp  = tid >> 2;              // 0..31 local row pair
    const int lr0 = rp * 2, lr1 = rp * 2 + 1;
    const int b0  = (tid & 3) * 8;
    const int row0 = (lr0 >> 4) * HID + cb * 16 + (lr0 & 15);
    const int row1 = (lr1 >> 4) * HID + cb * 16 + (lr1 & 15);
    const float4* wp0 = (const float4*)(whh + (size_t)row0 * HID);
    const float4* wp1 = (const float4*)(whh + (size_t)row1 * HID);

    // c-state ownership: 4 (unit,batch) pairs per thread
    float cst[4];
    int uu[4], bb[4];
#pragma unroll
    for (int q = 0; q < 4; q++) {
        int p = q * 128 + tid;
        uu[q] = p >> 5;            // local unit 0..15
        bb[q] = p & 31;            // batch
        size_t sidx = (size_t)(2 * layer + dir) * BATCH * HID +
                      (size_t)bb[q] * HID + cb * 16 + uu[q];
        cst[q] = c0[sidx];
        __stcg(&g_hT[dir][0][(cb * 16 + uu[q]) * BATCH + bb[q]], h0[sidx]);
    }

    unsigned sense = 0;
    grid_barrier(dir, sense);   // publish initial h

    for (int t = 0; t < T_STEPS; t++) {
        const int par = t & 1;
        const int te  = dir ? (T_STEPS - 1 - t) : t;

        // stage h (128 KB) into smem, L2-coherent
        {
            const float4* s4 = (const float4*)g_hT[dir][par];
            float4* d4 = (float4*)hs;
#pragma unroll 4
            for (int i = tid; i < HID * BATCH / 4; i += 128)
                d4[i] = __ldcg(s4 + i);
        }
        __syncthreads();

        // GEMV: 2 rows x 8 batches, FFMA2 over batch pairs
        ull acc[2][4];
#pragma unroll
        for (int r = 0; r < 2; r++)
#pragma unroll
            for (int j = 0; j < 4; j++) acc[r][j] = 0ULL;

#pragma unroll 2
        for (int k4 = 0; k4 < HID / 4; k4++) {
            float4 w0 = wp0[k4];
            float4 w1 = wp1[k4];
            const float* hbase = hs + k4 * 4 * BATCH + b0;
#define KSTEP(WX0, WX1, OFF)                                                 \
            {                                                                \
                ulonglong2 hA = *(const ulonglong2*)(hbase + (OFF));         \
                ulonglong2 hB = *(const ulonglong2*)(hbase + (OFF) + 4);     \
                ull w0p = pack2(WX0, WX0);                                   \
                ull w1p = pack2(WX1, WX1);                                   \
                acc[0][0] = ffma2(w0p, hA.x, acc[0][0]);                     \
                acc[0][1] = ffma2(w0p, hA.y, acc[0][1]);                     \
                acc[0][2] = ffma2(w0p, hB.x, acc[0][2]);                     \
                acc[0][3] = ffma2(w0p, hB.y, acc[0][3]);                     \
                acc[1][0] = ffma2(w1p, hA.x, acc[1][0]);                     \
                acc[1][1] = ffma2(w1p, hA.y, acc[1][1]);                     \
                acc[1][2] = ffma2(w1p, hB.x, acc[1][2]);                     \
                acc[1][3] = ffma2(w1p, hB.y, acc[1][3]);                     \
            }
            KSTEP(w0.x, w1.x, 0 * BATCH)
            KSTEP(w0.y, w1.y, 1 * BATCH)
            KSTEP(w0.z, w1.z, 2 * BATCH)
            KSTEP(w0.w, w1.w, 3 * BATCH)
#undef KSTEP
        }

        // add gx, write gate buffer
        {
            const float* gxrow = gxd + (size_t)te * BATCH * GDIM;
#pragma unroll
            for (int r = 0; r < 2; r++) {
                const int lr   = r ? lr1 : lr0;
                const int rowG = r ? row1 : row0;
                float* gb_ = gbuf + lr * 33 + b0;
#pragma unroll
                for (int jp = 0; jp < 4; jp++) {
                    float2 v = unpack2(acc[r][jp]);
                    int b = b0 + jp * 2;
                    gb_[jp * 2 + 0] = v.x + __ldcs(gxrow + (size_t)(b + 0) * GDIM + rowG);
                    gb_[jp * 2 + 1] = v.y + __ldcs(gxrow + (size_t)(b + 1) * GDIM + rowG);
                }
            }
        }
        __syncthreads();

        // gate combine + state update + outputs
#pragma unroll
        for (int q = 0; q < 4; q++) {
            int u = uu[q], b = bb[q];
            float iv = hsig (gbuf[( 0 + u) * 33 + b]);
            float fv = hsig (gbuf[(16 + u) * 33 + b]);
            float gv = clip1(gbuf[(32 + u) * 33 + b]);
            float ov = hsig (gbuf[(48 + u) * 33 + b]);
            float c  = fv * cst[q] + iv * gv;
            cst[q]   = c;
            float h  = ov * clip1(c);
            __stcg(&g_hT[dir][par ^ 1][(cb * 16 + u) * BATCH + b], h);
            yout[(size_t)te * BATCH * YW + (size_t)b * YW + dir * HID + cb * 16 + u] = h;
        }

        if (t < T_STEPS - 1) grid_barrier(dir, sense);
    }
}

// ---------------- launch ----------------
extern "C" void kernel_launch(void* const* d_in, const int* in_sizes, int n_in,
                              void* d_out, int out_size)
{
    (void)in_sizes; (void)n_in; (void)out_size;

    const float* x  = (const float*)d_in[0];
    const float* h0 = (const float*)d_in[1];
    const float* c0 = (const float*)d_in[2];
    const float* P[24];
    for (int i = 0; i < 24; i++) P[i] = (const float*)d_in[3 + i];
    // P[(l*2+d)*4 + {0:w_ih, 1:w_hh, 2:b_ih, 3:b_hh}]

    float *gx = nullptr, *yb = nullptr;
    cudaGetSymbolAddress((void**)&gx, g_gx);
    cudaGetSymbolAddress((void**)&yb, g_ybuf);
    cudaFuncSetAttribute(rec_kernel, cudaFuncAttributeMaxDynamicSharedMemorySize, REC_SMEM);

    float* y0  = yb;
    float* y1  = yb + (size_t)MROWS * YW;
    float* out = (float*)d_out;

    dim3 gb(256), gg(GDIM / 128, MROWS / 128, 2);

    // layer 0  (K = 320)
    gemm_bias<<<gg, gb>>>(x, 320, gx, P[0], P[2], P[3], P[4], P[6], P[7]);
    rec_kernel<<<128, 128, REC_SMEM>>>(P[1], P[5], h0, c0, 0, gx, y0);

    // layer 1  (K = 2048)
    gemm_bias<<<gg, gb>>>(y0, 2048, gx, P[8], P[10], P[11], P[12], P[14], P[15]);
    rec_kernel<<<128, 128, REC_SMEM>>>(P[9], P[13], h0, c0, 1, gx, y1);

    // layer 2  (K = 2048)
    gemm_bias<<<gg, gb>>>(y1, 2048, gx, P[16], P[18], P[19], P[20], P[22], P[23]);
    rec_kernel<<<128, 128, REC_SMEM>>>(P[17], P[21], h0, c0, 2, gx, out);
}

// round 5
// speedup vs baseline: 1.2995x; 1.2419x over previous
#include <cuda_runtime.h>
#include <cuda_bf16.h>
#include <cstdint>
#include <cstddef>

#define T_STEPS 512
#define BATCH   32
#define HID     1024
#define GDIM    4096
#define MROWS   16384          // T*B
#define YW      2048           // 2*H
#define REC_SMEM (HID*BATCH*4 + 64*33*4)   // 139520 B

typedef unsigned long long ull;

// ---------------- device scratch (no runtime allocation) ----------------
__device__ float g_gx[134217728];        // [2][MROWS][GDIM]  512 MB
__device__ float g_ybuf[67108864];       // [2][MROWS][YW]    256 MB
__device__ float g_hT[2][2][HID*BATCH];  // [dir][parity][u*32+b]
__device__ unsigned g_bar_cnt[2]   = {0, 0};
__device__ unsigned g_bar_phase[2] = {0, 0};
// bf16 split planes
__device__ __nv_bfloat16 g_whi[36700160];   // weights hi (all 6 w_ih)
__device__ __nv_bfloat16 g_wlo[36700160];   // weights lo
__device__ __nv_bfloat16 g_ahi[33554432];   // activations hi [16384 x <=2048]
__device__ __nv_bfloat16 g_alo[33554432];   // activations lo

// ---------------- helpers ----------------
__device__ __forceinline__ uint32_t smem_u32(const void* p) {
    uint32_t a;
    asm("{ .reg .u64 t; cvta.to.shared.u64 t, %1; cvt.u32.u64 %0, t; }" : "=r"(a) : "l"(p));
    return a;
}
#define SW128(o) ((o) ^ (((o) >> 3) & 0x70))

// mma.sync bf16 (compute_80+, runs on sm_100 legacy HMMA path)
#define MMA_BF16(d, a, b0v, b1v)                                              \
    asm volatile("mma.sync.aligned.m16n8k16.row.col.f32.bf16.bf16.f32 "       \
        "{%0,%1,%2,%3}, {%4,%5,%6,%7}, {%8,%9}, {%0,%1,%2,%3};"               \
        : "+f"((d)[0]), "+f"((d)[1]), "+f"((d)[2]), "+f"((d)[3])              \
        : "r"((a)[0]), "r"((a)[1]), "r"((a)[2]), "r"((a)[3]),                 \
          "r"(b0v), "r"(b1v))

#define LDSM4(r, addr)                                                        \
    asm volatile("ldmatrix.sync.aligned.m8n8.x4.shared.b16 "                  \
        "{%0,%1,%2,%3}, [%4];"                                                \
        : "=r"((r)[0]), "=r"((r)[1]), "=r"((r)[2]), "=r"((r)[3])              \
        : "r"(addr))

// packed fp32 helpers
__device__ __forceinline__ ull ffma2(ull a, ull b, ull c) {
    ull d;
    asm("fma.rn.f32x2 %0, %1, %2, %3;" : "=l"(d) : "l"(a), "l"(b), "l"(c));
    return d;
}
__device__ __forceinline__ ull pack2(float x, float y) {
    ull r; asm("mov.b64 %0, {%1, %2};" : "=l"(r) : "f"(x), "f"(y)); return r;
}
__device__ __forceinline__ float2 unpack2(ull v) {
    float2 r; asm("mov.b64 {%0, %1}, %2;" : "=f"(r.x), "=f"(r.y) : "l"(v)); return r;
}

__device__ __forceinline__ float hsig(float v)  { return fminf(fmaxf(fmaf(v, 0.2f, 0.5f), 0.0f), 1.0f); }
__device__ __forceinline__ float clip1(float v) { return fminf(fmaxf(v, -1.0f), 1.0f); }

__device__ __forceinline__ void grid_barrier(int dir, unsigned& sense) {
    __syncthreads();
    __threadfence();
    sense ^= 1u;
    if (threadIdx.x == 0) {
        if (atomicAdd(&g_bar_cnt[dir], 1u) == 63u) {
            atomicExch(&g_bar_cnt[dir], 0u);
            __threadfence();
            atomicExch(&g_bar_phase[dir], sense);
        } else {
            while (atomicAdd(&g_bar_phase[dir], 0u) != sense) { __nanosleep(64); }
        }
    }
    __syncthreads();
    __threadfence();
}

// ---------------- fp32 -> bf16 hi/lo split ----------------
__global__ void __launch_bounds__(256)
cvt_split(const float4* __restrict__ src, __nv_bfloat16* __restrict__ hi,
          __nv_bfloat16* __restrict__ lo, int n4)
{
    int i = blockIdx.x * 256 + threadIdx.x;
    if (i >= n4) return;
    float4 v = src[i];
    __nv_bfloat16 h0 = __float2bfloat16_rn(v.x);
    __nv_bfloat16 h1 = __float2bfloat16_rn(v.y);
    __nv_bfloat16 h2 = __float2bfloat16_rn(v.z);
    __nv_bfloat16 h3 = __float2bfloat16_rn(v.w);
    __nv_bfloat16 l0 = __float2bfloat16_rn(v.x - __bfloat162float(h0));
    __nv_bfloat16 l1 = __float2bfloat16_rn(v.y - __bfloat162float(h1));
    __nv_bfloat16 l2 = __float2bfloat16_rn(v.z - __bfloat162float(h2));
    __nv_bfloat16 l3 = __float2bfloat16_rn(v.w - __bfloat162float(h3));
    __nv_bfloat162* H = (__nv_bfloat162*)hi + i * 2;
    __nv_bfloat162* L = (__nv_bfloat162*)lo + i * 2;
    H[0] = __nv_bfloat162(h0, h1); H[1] = __nv_bfloat162(h2, h3);
    L[0] = __nv_bfloat162(l0, l1); L[1] = __nv_bfloat162(l2, l3);
}

// ---------------- tensor-core input-projection GEMM (mma.sync bf16) ----------------
// D[m][n] = sum_k A[m][k]*W[n][k] + b1[n] + b2[n], bf16 split (hh + hl + lh).
// CTA 128x128 tile, 256 threads = 8 warps (2m x 4n), warp tile 64x32, K-chunk 64.
#define SMO_AHI 0
#define SMO_ALO 16384
#define SMO_BHI 32768
#define SMO_BLO 49152
#define SMO_BIAS 65536
#define GEMM_SMEM (65536 + 512)

__global__ void __launch_bounds__(256)
gemm_mma(int K,
         const __nv_bfloat16* __restrict__ Ahi, const __nv_bfloat16* __restrict__ Alo,
         const __nv_bfloat16* __restrict__ WhiF, const __nv_bfloat16* __restrict__ WloF,
         const __nv_bfloat16* __restrict__ WhiR, const __nv_bfloat16* __restrict__ WloR,
         const float* __restrict__ bf1, const float* __restrict__ bf2,
         const float* __restrict__ br1, const float* __restrict__ br2,
         float* __restrict__ G)
{
    extern __shared__ char sm[];
    const uint32_t smb = smem_u32(sm);
    const int tid  = threadIdx.x;
    const int wid  = tid >> 5;
    const int lane = tid & 31;
    const int z    = blockIdx.z;

    const __nv_bfloat16* __restrict__ Whi = z ? WhiR : WhiF;
    const __nv_bfloat16* __restrict__ Wlo = z ? WloR : WloF;
    const float* __restrict__ b1 = z ? br1 : bf1;
    const float* __restrict__ b2 = z ? br2 : bf2;
    float* __restrict__ Gz = G + (size_t)z * MROWS * GDIM;

    const int n0 = blockIdx.x * 128;
    const int m0 = blockIdx.y * 128;
    const int wm = (wid >> 2) * 64;    // warp m offset in tile
    const int wn = (wid & 3) * 32;     // warp n offset in tile

    {   // bias staging
        float* bias = (float*)(sm + SMO_BIAS);
        if (tid < 128) bias[tid] = b1[n0 + tid] + b2[n0 + tid];
    }

    float acc[4][4][4];
#pragma unroll
    for (int mi = 0; mi < 4; mi++)
#pragma unroll
        for (int ni = 0; ni < 4; ni++)
#pragma unroll
            for (int e = 0; e < 4; e++) acc[mi][ni][e] = 0.0f;

    // per-thread staging coords: 1024 uint4 per tile, 4 per thread
    const int sr = tid >> 3;              // base row (this thread's v>>3 for i=0.. no: v=tid+i*256)
    (void)sr;

    const int nchunk = K >> 6;
    for (int ch = 0; ch < nchunk; ch++) {
        const int kc = ch * 64;
        __syncthreads();
#pragma unroll
        for (int i = 0; i < 4; i++) {
            int v = tid + i * 256;        // 0..1023
            int r = v >> 3;               // row 0..127
            int c = v & 7;                // 16B col 0..7
            uint32_t so = SW128((uint32_t)(r * 128 + c * 16));
            size_t ga = (size_t)(m0 + r) * K + kc + c * 8;
            size_t gb = (size_t)(n0 + r) * K + kc + c * 8;
            *(uint4*)(sm + SMO_AHI + so) = *(const uint4*)(Ahi + ga);
            *(uint4*)(sm + SMO_ALO + so) = *(const uint4*)(Alo + ga);
            *(uint4*)(sm + SMO_BHI + so) = *(const uint4*)(Whi + gb);
            *(uint4*)(sm + SMO_BLO + so) = *(const uint4*)(Wlo + gb);
        }
        __syncthreads();

#pragma unroll
        for (int ks = 0; ks < 4; ks++) {
            uint32_t ah[4][4], al[4][4], bh[2][4], bl[2][4];
#pragma unroll
            for (int mi = 0; mi < 4; mi++) {
                uint32_t off = SW128((uint32_t)(
                    (wm + mi * 16 + (lane & 15)) * 128 + ks * 32 + (lane >> 4) * 16));
                LDSM4(ah[mi], smb + SMO_AHI + off);
                LDSM4(al[mi], smb + SMO_ALO + off);
            }
#pragma unroll
            for (int p = 0; p < 2; p++) {
                int q  = lane >> 3;
                int nf = q >> 1, kl = q & 1;
                uint32_t off = SW128((uint32_t)(
                    (wn + p * 16 + nf * 8 + (lane & 7)) * 128 + ks * 32 + kl * 16));
                LDSM4(bh[p], smb + SMO_BHI + off);
                LDSM4(bl[p], smb + SMO_BLO + off);
            }
#pragma unroll
            for (int mi = 0; mi < 4; mi++) {
#pragma unroll
                for (int ni = 0; ni < 4; ni++) {
                    const int p = ni >> 1, s = (ni & 1) * 2;
                    MMA_BF16(acc[mi][ni], ah[mi], bh[p][s], bh[p][s + 1]);   // hh
                    MMA_BF16(acc[mi][ni], ah[mi], bl[p][s], bl[p][s + 1]);   // hl
                    MMA_BF16(acc[mi][ni], al[mi], bh[p][s], bh[p][s + 1]);   // lh
                }
            }
        }
    }

    // epilogue: direct gmem stores + bias
    const float* bias = (const float*)(sm + SMO_BIAS);
    const int qr = lane >> 2;           // 0..7
    const int qc = (lane & 3) * 2;      // 0,2,4,6
#pragma unroll
    for (int mi = 0; mi < 4; mi++) {
#pragma unroll
        for (int ni = 0; ni < 4; ni++) {
            int col = wn + ni * 8 + qc;
            float bx = bias[col], by = bias[col + 1];
            size_t base0 = (size_t)(m0 + wm + mi * 16 + qr) * GDIM + n0 + col;
            size_t base1 = base0 + (size_t)8 * GDIM;
            *(float2*)&Gz[base0] = make_float2(acc[mi][ni][0] + bx, acc[mi][ni][1] + by);
            *(float2*)&Gz[base1] = make_float2(acc[mi][ni][2] + bx, acc[mi][ni][3] + by);
        }
    }
}

// ---------------- persistent bidirectional recurrence ----------------
// 128 CTAs x 256 threads. dir = blockIdx.x>>6; CTA owns 16 units (64 gate rows).
__global__ void __launch_bounds__(256)
rec_kernel(const float* __restrict__ whhF, const float* __restrict__ whhR,
           const float* __restrict__ h0,  const float* __restrict__ c0,
           int layer, const float* __restrict__ gx, float* __restrict__ yout)
{
    extern __shared__ float smem[];
    float* hs   = smem;                 // [1024][32]
    float* gbuf = smem + HID * BATCH;   // [64][33] padded

    const int tid = threadIdx.x;
    const int dir = blockIdx.x >> 6;
    const int cb  = blockIdx.x & 63;
    const float* __restrict__ whh = dir ? whhR : whhF;
    const float* __restrict__ gxd = gx + (size_t)dir * MROWS * GDIM;

    const int rr  = tid >> 2;              // 0..63 local gate row
    const int b0  = (tid & 3) * 8;
    const int row = (rr >> 4) * HID + cb * 16 + (rr & 15);
    const float4* __restrict__ wp = (const float4*)(whh + (size_t)row * HID);

    float cst[2];
    int uu[2], bb[2];
#pragma unroll
    for (int q = 0; q < 2; q++) {
        int p = q * 256 + tid;
        uu[q] = p >> 5;
        bb[q] = p & 31;
        size_t sidx = (size_t)(2 * layer + dir) * BATCH * HID +
                      (size_t)bb[q] * HID + cb * 16 + uu[q];
        cst[q] = c0[sidx];
        __stcg(&g_hT[dir][0][(cb * 16 + uu[q]) * BATCH + bb[q]], h0[sidx]);
    }

    unsigned sense = 0;
    grid_barrier(dir, sense);

    for (int t = 0; t < T_STEPS; t++) {
        const int par = t & 1;
        const int te  = dir ? (T_STEPS - 1 - t) : t;

        {
            const float4* s4 = (const float4*)g_hT[dir][par];
            float4* d4 = (float4*)hs;
#pragma unroll 8
            for (int i = tid; i < HID * BATCH / 4; i += 256)
                d4[i] = __ldcg(s4 + i);
        }
        __syncthreads();

        ull a0 = 0, a1 = 0, a2 = 0, a3 = 0;
        float4 wv = wp[0];
#pragma unroll 2
        for (int k4 = 0; k4 < HID / 4; k4++) {
            float4 wn_ = wp[(k4 + 1) & (HID / 4 - 1)];
            const float* hbase = hs + k4 * 4 * BATCH + b0;
#define KSTEP(WX, OFF)                                                       \
            {                                                                \
                ulonglong2 hA = *(const ulonglong2*)(hbase + (OFF));         \
                ulonglong2 hB = *(const ulonglong2*)(hbase + (OFF) + 4);     \
                ull wpk = pack2(WX, WX);                                     \
                a0 = ffma2(wpk, hA.x, a0);                                   \
                a1 = ffma2(wpk, hA.y, a1);                                   \
                a2 = ffma2(wpk, hB.x, a2);                                   \
                a3 = ffma2(wpk, hB.y, a3);                                   \
            }
            KSTEP(wv.x, 0 * BATCH)
            KSTEP(wv.y, 1 * BATCH)
            KSTEP(wv.z, 2 * BATCH)
            KSTEP(wv.w, 3 * BATCH)
#undef KSTEP
            wv = wn_;
        }

        {
            const float* gxrow = gxd + (size_t)te * BATCH * GDIM + row;
            float* gb_ = gbuf + rr * 33 + b0;
            float2 v;
            v = unpack2(a0);
            gb_[0] = v.x + __ldcs(gxrow + (size_t)(b0 + 0) * GDIM);
            gb_[1] = v.y + __ldcs(gxrow + (size_t)(b0 + 1) * GDIM);
            v = unpack2(a1);
            gb_[2] = v.x + __ldcs(gxrow + (size_t)(b0 + 2) * GDIM);
            gb_[3] = v.y + __ldcs(gxrow + (size_t)(b0 + 3) * GDIM);
            v = unpack2(a2);
            gb_[4] = v.x + __ldcs(gxrow + (size_t)(b0 + 4) * GDIM);
            gb_[5] = v.y + __ldcs(gxrow + (size_t)(b0 + 5) * GDIM);
            v = unpack2(a3);
            gb_[6] = v.x + __ldcs(gxrow + (size_t)(b0 + 6) * GDIM);
            gb_[7] = v.y + __ldcs(gxrow + (size_t)(b0 + 7) * GDIM);
        }
        __syncthreads();

#pragma unroll
        for (int q = 0; q < 2; q++) {
            int u = uu[q], b = bb[q];
            float iv = hsig (gbuf[( 0 + u) * 33 + b]);
            float fv = hsig (gbuf[(16 + u) * 33 + b]);
            float gv = clip1(gbuf[(32 + u) * 33 + b]);
            float ov = hsig (gbuf[(48 + u) * 33 + b]);
            float c  = fv * cst[q] + iv * gv;
            cst[q]   = c;
            float h  = ov * clip1(c);
            __stcg(&g_hT[dir][par ^ 1][(cb * 16 + u) * BATCH + b], h);
            yout[(size_t)te * BATCH * YW + (size_t)b * YW + dir * HID + cb * 16 + u] = h;
        }

        if (t < T_STEPS - 1) grid_barrier(dir, sense);
    }
}

// ---------------- launch ----------------
extern "C" void kernel_launch(void* const* d_in, const int* in_sizes, int n_in,
                              void* d_out, int out_size)
{
    (void)in_sizes; (void)n_in; (void)out_size;

    const float* x  = (const float*)d_in[0];
    const float* h0 = (const float*)d_in[1];
    const float* c0 = (const float*)d_in[2];
    const float* P[24];
    for (int i = 0; i < 24; i++) P[i] = (const float*)d_in[3 + i];
    // P[(l*2+d)*4 + {0:w_ih, 1:w_hh, 2:b_ih, 3:b_hh}]

    float *gx = nullptr, *yb = nullptr;
    __nv_bfloat16 *whi = nullptr, *wlo = nullptr, *ahi = nullptr, *alo = nullptr;
    cudaGetSymbolAddress((void**)&gx,  g_gx);
    cudaGetSymbolAddress((void**)&yb,  g_ybuf);
    cudaGetSymbolAddress((void**)&whi, g_whi);
    cudaGetSymbolAddress((void**)&wlo, g_wlo);
    cudaGetSymbolAddress((void**)&ahi, g_ahi);
    cudaGetSymbolAddress((void**)&alo, g_alo);
    cudaFuncSetAttribute(rec_kernel, cudaFuncAttributeMaxDynamicSharedMemorySize, REC_SMEM);
    cudaFuncSetAttribute(gemm_mma,   cudaFuncAttributeMaxDynamicSharedMemorySize, GEMM_SMEM);

    float* y0  = yb;
    float* y1  = yb + (size_t)MROWS * YW;
    float* out = (float*)d_out;

    // weight split conversion (w_ih only; w_hh stays fp32 for the recurrence)
    const size_t woff[6] = {0, 1310720, 2621440, 11010048, 19398656, 27787264};
    const int    wsz [6] = {1310720, 1310720, 8388608, 8388608, 8388608, 8388608};
    const int    wsrc[6] = {0, 4, 8, 12, 16, 20};
    for (int i = 0; i < 6; i++) {
        int n4 = wsz[i] / 4;
        cvt_split<<<(n4 + 255) / 256, 256>>>((const float4*)P[wsrc[i]],
                                             whi + woff[i], wlo + woff[i], n4);
    }

    dim3 gg(GDIM / 128, MROWS / 128, 2), gb(256);

    // layer 0 (K = 320)
    cvt_split<<<(MROWS * 320 / 4 + 255) / 256, 256>>>((const float4*)x, ahi, alo, MROWS * 320 / 4);
    gemm_mma<<<gg, gb, GEMM_SMEM>>>(320, ahi, alo,
                                    whi + woff[0], wlo + woff[0], whi + woff[1], wlo + woff[1],
                                    P[2], P[3], P[6], P[7], gx);
    rec_kernel<<<128, 256, REC_SMEM>>>(P[1], P[5], h0, c0, 0, gx, y0);

    // layer 1 (K = 2048)
    cvt_split<<<(MROWS * 2048 / 4 + 255) / 256, 256>>>((const float4*)y0, ahi, alo, MROWS * 2048 / 4);
    gemm_mma<<<gg, gb, GEMM_SMEM>>>(2048, ahi, alo,
                                    whi + woff[2], wlo + woff[2], whi + woff[3], wlo + woff[3],
                                    P[10], P[11], P[14], P[15], gx);
    rec_kernel<<<128, 256, REC_SMEM>>>(P[9], P[13], h0, c0, 1, gx, y1);

    // layer 2 (K = 2048)
    cvt_split<<<(MROWS * 2048 / 4 + 255) / 256, 256>>>((const float4*)y1, ahi, alo, MROWS * 2048 / 4);
    gemm_mma<<<gg, gb, GEMM_SMEM>>>(2048, ahi, alo,
                                    whi + woff[4], wlo + woff[4], whi + woff[5], wlo + woff[5],
                                    P[18], P[19], P[22], P[23], gx);
    rec_kernel<<<128, 256, REC_SMEM>>>(P[17], P[21], h0, c0, 2, gx, out);
}

// round 6
// speedup vs baseline: 3.3237x; 2.5578x over previous
#include <cuda_runtime.h>
#include <cuda_bf16.h>
#include <cstdint>
#include <cstddef>

#define T_STEPS 512
#define BATCH   32
#define HID     1024
#define GDIM    4096
#define MROWS   16384          // T*B
#define YW      2048           // 2*H

typedef unsigned long long ull;

// ---------------- device scratch (no runtime allocation) ----------------
__device__ float g_gx[134217728];        // [2][MROWS][GDIM]  512 MB
__device__ float g_ybuf[67108864];       // [2][MROWS][YW]    256 MB
__device__ __nv_bfloat16 g_hB[2][2][2][32 * 1024]; // [dir][parity][plane][b*1024+k]
__device__ unsigned g_bar_cnt[2]   = {0, 0};
__device__ unsigned g_bar_phase[2] = {0, 0};
// bf16 split planes for input GEMM
__device__ __nv_bfloat16 g_whi[36700160];   // w_ih hi (all 6)
__device__ __nv_bfloat16 g_wlo[36700160];   // w_ih lo
__device__ __nv_bfloat16 g_ahi[33554432];   // activations hi
__device__ __nv_bfloat16 g_alo[33554432];   // activations lo
// W_hh baked smem images: [ld 6][cb 64][blk 16] x 16KB (hi plane @0, lo @8192)
__device__ uint4 g_wrec[6291456];           // 100.66 MB

// ---------------- helpers ----------------
__device__ __forceinline__ uint32_t smem_u32(const void* p) {
    uint32_t a;
    asm("{ .reg .u64 t; cvta.to.shared.u64 t, %1; cvt.u32.u64 %0, t; }" : "=r"(a) : "l"(p));
    return a;
}
#define SW128(o) ((o) ^ (((o) >> 3) & 0x70))

#define MMA_BF16(d, a, b0v, b1v)                                              \
    asm volatile("mma.sync.aligned.m16n8k16.row.col.f32.bf16.bf16.f32 "       \
        "{%0,%1,%2,%3}, {%4,%5,%6,%7}, {%8,%9}, {%0,%1,%2,%3};"               \
        : "+f"((d)[0]), "+f"((d)[1]), "+f"((d)[2]), "+f"((d)[3])              \
        : "r"((a)[0]), "r"((a)[1]), "r"((a)[2]), "r"((a)[3]),                 \
          "r"(b0v), "r"(b1v))

#define LDSM4(r, addr)                                                        \
    asm volatile("ldmatrix.sync.aligned.m8n8.x4.shared.b16 "                  \
        "{%0,%1,%2,%3}, [%4];"                                                \
        : "=r"((r)[0]), "=r"((r)[1]), "=r"((r)[2]), "=r"((r)[3])              \
        : "r"(addr))

__device__ __forceinline__ float hsig(float v)  { return fminf(fmaxf(fmaf(v, 0.2f, 0.5f), 0.0f), 1.0f); }
__device__ __forceinline__ float clip1(float v) { return fminf(fmaxf(v, -1.0f), 1.0f); }

__device__ __forceinline__ void grid_barrier(int dir, unsigned& sense) {
    __syncthreads();
    __threadfence();
    sense ^= 1u;
    if (threadIdx.x == 0) {
        if (atomicAdd(&g_bar_cnt[dir], 1u) == 63u) {
            atomicExch(&g_bar_cnt[dir], 0u);
            __threadfence();
            atomicExch(&g_bar_phase[dir], sense);
        } else {
            while (atomicAdd(&g_bar_phase[dir], 0u) != sense) { __nanosleep(64); }
        }
    }
    __syncthreads();
    __threadfence();
}

// ---------------- fp32 -> bf16 hi/lo split ----------------
__global__ void __launch_bounds__(256)
cvt_split(const float4* __restrict__ src, __nv_bfloat16* __restrict__ hi,
          __nv_bfloat16* __restrict__ lo, int n4)
{
    int i = blockIdx.x * 256 + threadIdx.x;
    if (i >= n4) return;
    float4 v = src[i];
    __nv_bfloat16 h0 = __float2bfloat16_rn(v.x);
    __nv_bfloat16 h1 = __float2bfloat16_rn(v.y);
    __nv_bfloat16 h2 = __float2bfloat16_rn(v.z);
    __nv_bfloat16 h3 = __float2bfloat16_rn(v.w);
    __nv_bfloat16 l0 = __float2bfloat16_rn(v.x - __bfloat162float(h0));
    __nv_bfloat16 l1 = __float2bfloat16_rn(v.y - __bfloat162float(h1));
    __nv_bfloat16 l2 = __float2bfloat16_rn(v.z - __bfloat162float(h2));
    __nv_bfloat16 l3 = __float2bfloat16_rn(v.w - __bfloat162float(h3));
    __nv_bfloat162* H = (__nv_bfloat162*)hi + i * 2;
    __nv_bfloat162* L = (__nv_bfloat162*)lo + i * 2;
    H[0] = __nv_bfloat162(h0, h1); H[1] = __nv_bfloat162(h2, h3);
    L[0] = __nv_bfloat162(l0, l1); L[1] = __nv_bfloat162(l2, l3);
}

// ---------------- W_hh prep: bake hi/lo SW128 smem images ----------------
struct W6 { const float* w[6]; };

__global__ void __launch_bounds__(256)
wrec_prep(W6 p, uint4* __restrict__ out)
{
    int v  = blockIdx.x * 256 + threadIdx.x;  // 0..524287 chunk within ld
    int ld = blockIdx.y;
    int row = v >> 7;                // 0..4095 W_hh row
    int k   = (v & 127) * 8;         // 0..1016
    const float* w = p.w[ld];
    const float* s = w + (size_t)row * HID + k;
    float f[8];
#pragma unroll
    for (int j = 0; j < 8; j++) f[j] = s[j];
    unsigned short hi[8], lo[8];
#pragma unroll
    for (int j = 0; j < 8; j++) {
        __nv_bfloat16 h = __float2bfloat16_rn(f[j]);
        __nv_bfloat16 l = __float2bfloat16_rn(f[j] - __bfloat162float(h));
        hi[j] = *(unsigned short*)&h;
        lo[j] = *(unsigned short*)&l;
    }
    int gate = row >> 10, uidx = row & 1023;
    int cb = uidx >> 4, ul = uidx & 15;
    int rl = gate * 16 + ul;          // local row 0..63
    int blk = k >> 6, c = k & 63;
    size_t img = ((size_t)(ld * 64 + cb) * 16 + blk) * 16384;  // bytes
    uint32_t off = SW128((uint32_t)(rl * 128 + c * 2));
    char* ob = (char*)out;
    *(uint4*)(ob + img + off)        = *(uint4*)hi;
    *(uint4*)(ob + img + 8192 + off) = *(uint4*)lo;
}

// ---------------- tensor-core input-projection GEMM (unchanged, passing) ----------------
#define SMO_AHI 0
#define SMO_ALO 16384
#define SMO_BHI 32768
#define SMO_BLO 49152
#define SMO_BIAS 65536
#define GEMM_SMEM (65536 + 512)

__global__ void __launch_bounds__(256)
gemm_mma(int K,
         const __nv_bfloat16* __restrict__ Ahi, const __nv_bfloat16* __restrict__ Alo,
         const __nv_bfloat16* __restrict__ WhiF, const __nv_bfloat16* __restrict__ WloF,
         const __nv_bfloat16* __restrict__ WhiR, const __nv_bfloat16* __restrict__ WloR,
         const float* __restrict__ bf1, const float* __restrict__ bf2,
         const float* __restrict__ br1, const float* __restrict__ br2,
         float* __restrict__ G)
{
    extern __shared__ char sm[];
    const uint32_t smb = smem_u32(sm);
    const int tid  = threadIdx.x;
    const int wid  = tid >> 5;
    const int lane = tid & 31;
    const int z    = blockIdx.z;

    const __nv_bfloat16* __restrict__ Whi = z ? WhiR : WhiF;
    const __nv_bfloat16* __restrict__ Wlo = z ? WloR : WloF;
    const float* __restrict__ b1 = z ? br1 : bf1;
    const float* __restrict__ b2 = z ? br2 : bf2;
    float* __restrict__ Gz = G + (size_t)z * MROWS * GDIM;

    const int n0 = blockIdx.x * 128;
    const int m0 = blockIdx.y * 128;
    const int wm = (wid >> 2) * 64;
    const int wn = (wid & 3) * 32;

    {
        float* bias = (float*)(sm + SMO_BIAS);
        if (tid < 128) bias[tid] = b1[n0 + tid] + b2[n0 + tid];
    }

    float acc[4][4][4];
#pragma unroll
    for (int mi = 0; mi < 4; mi++)
#pragma unroll
        for (int ni = 0; ni < 4; ni++)
#pragma unroll
            for (int e = 0; e < 4; e++) acc[mi][ni][e] = 0.0f;

    const int nchunk = K >> 6;
    for (int ch = 0; ch < nchunk; ch++) {
        const int kc = ch * 64;
        __syncthreads();
#pragma unroll
        for (int i = 0; i < 4; i++) {
            int v = tid + i * 256;
            int r = v >> 3;
            int c = v & 7;
            uint32_t so = SW128((uint32_t)(r * 128 + c * 16));
            size_t ga = (size_t)(m0 + r) * K + kc + c * 8;
            size_t gb = (size_t)(n0 + r) * K + kc + c * 8;
            *(uint4*)(sm + SMO_AHI + so) = *(const uint4*)(Ahi + ga);
            *(uint4*)(sm + SMO_ALO + so) = *(const uint4*)(Alo + ga);
            *(uint4*)(sm + SMO_BHI + so) = *(const uint4*)(Whi + gb);
            *(uint4*)(sm + SMO_BLO + so) = *(const uint4*)(Wlo + gb);
        }
        __syncthreads();

#pragma unroll
        for (int ks = 0; ks < 4; ks++) {
            uint32_t ah[4][4], al[4][4], bh[2][4], bl[2][4];
#pragma unroll
            for (int mi = 0; mi < 4; mi++) {
                uint32_t off = SW128((uint32_t)(
                    (wm + mi * 16 + (lane & 15)) * 128 + ks * 32 + (lane >> 4) * 16));
                LDSM4(ah[mi], smb + SMO_AHI + off);
                LDSM4(al[mi], smb + SMO_ALO + off);
            }
#pragma unroll
            for (int p = 0; p < 2; p++) {
                int q  = lane >> 3;
                int nf = q >> 1, kl = q & 1;
                uint32_t off = SW128((uint32_t)(
                    (wn + p * 16 + nf * 8 + (lane & 7)) * 128 + ks * 32 + kl * 16));
                LDSM4(bh[p], smb + SMO_BHI + off);
                LDSM4(bl[p], smb + SMO_BLO + off);
            }
#pragma unroll
            for (int mi = 0; mi < 4; mi++) {
#pragma unroll
                for (int ni = 0; ni < 4; ni++) {
                    const int p = ni >> 1, s = (ni & 1) * 2;
                    MMA_BF16(acc[mi][ni], ah[mi], bh[p][s], bh[p][s + 1]);
                    MMA_BF16(acc[mi][ni], ah[mi], bl[p][s], bl[p][s + 1]);
                    MMA_BF16(acc[mi][ni], al[mi], bh[p][s], bh[p][s + 1]);
                }
            }
        }
    }

    const float* bias = (const float*)(sm + SMO_BIAS);
    const int qr = lane >> 2;
    const int qc = (lane & 3) * 2;
#pragma unroll
    for (int mi = 0; mi < 4; mi++) {
#pragma unroll
        for (int ni = 0; ni < 4; ni++) {
            int col = wn + ni * 8 + qc;
            float bx = bias[col], by = bias[col + 1];
            size_t base0 = (size_t)(m0 + wm + mi * 16 + qr) * GDIM + n0 + col;
            size_t base1 = base0 + (size_t)8 * GDIM;
            *(float2*)&Gz[base0] = make_float2(acc[mi][ni][0] + bx, acc[mi][ni][1] + by);
            *(float2*)&Gz[base1] = make_float2(acc[mi][ni][2] + bx, acc[mi][ni][3] + by);
        }
    }
}

// ---------------- persistent tensor-core recurrence ----------------
// 128 CTAs x 256 threads (8 warps). dir = blockIdx.x>>6; CTA owns 16 units
// (64 gate rows) x 32 batch. Warp (mi = w>>1, nh = w&1): m16 tile x n16 half,
// full K=1024. W streamed from baked L2 images; h staged bf16 hi/lo in smem.
#define RSM_HA 0
#define RSM_HB 65536
#define RSM_W  131072
#define RSM_G  163840
#define REC2_SMEM (163840 + 64*33*4)   // 172288 B

__global__ void __launch_bounds__(256)
rec_kernel(const uint4* __restrict__ wrec,
           const float* __restrict__ h0, const float* __restrict__ c0,
           int layer, const float* __restrict__ gx, float* __restrict__ yout)
{
    extern __shared__ char sm[];
    const uint32_t smb = smem_u32(sm);
    float* Gbuf = (float*)(sm + RSM_G);

    const int tid  = threadIdx.x;
    const int lane = tid & 31;
    const int wrp  = tid >> 5;
    const int mi   = wrp >> 1;
    const int nh   = wrp & 1;
    const int dir  = blockIdx.x >> 6;
    const int cb   = blockIdx.x & 63;
    const int ld   = layer * 2 + dir;
    const float* __restrict__ gxd = gx + (size_t)dir * MROWS * GDIM;
    const uint4* __restrict__ wsrc = wrec + (size_t)(ld * 64 + cb) * 16 * 1024;

    // c-state: 2 (unit,batch) pairs per thread
    float cst[2];
    int uu[2], bb[2];
#pragma unroll
    for (int q = 0; q < 2; q++) {
        int p = q * 256 + tid;
        uu[q] = p >> 5;
        bb[q] = p & 31;
        size_t sidx = (size_t)(2 * layer + dir) * BATCH * HID +
                      (size_t)bb[q] * HID + cb * 16 + uu[q];
        cst[q] = c0[sidx];
        float hv = h0[sidx];
        __nv_bfloat16 hh = __float2bfloat16_rn(hv);
        __nv_bfloat16 hl = __float2bfloat16_rn(hv - __bfloat162float(hh));
        int gk = cb * 16 + uu[q];
        g_hB[dir][0][0][bb[q] * 1024 + gk] = hh;
        g_hB[dir][0][1][bb[q] * 1024 + gk] = hl;
    }

    unsigned sense = 0;
    grid_barrier(dir, sense);

    for (int t = 0; t < T_STEPS; t++) {
        const int par = t & 1;
        const int te  = dir ? (T_STEPS - 1 - t) : t;

        // stage h (2 planes x 64KB) into SW128 k64-blocks
        {
            const uint4* hsrc = (const uint4*)&g_hB[dir][par][0][0];
#pragma unroll
            for (int i = 0; i < 32; i++) {
                int v = tid + i * 256;
                int plane = v >> 12;
                int w = v & 4095;
                int b = w >> 7;
                int kq = w & 127;
                int blk = kq >> 3, cq = kq & 7;
                uint4 d = __ldcg(hsrc + v);
                *(uint4*)(sm + plane * 65536 + blk * 4096 +
                          SW128((uint32_t)(b * 128 + cq * 16))) = d;
            }
        }

        // prefetch gx for combine
        float gxv[2][4];
        {
            const float* gxs = gxd + (size_t)te * BATCH * GDIM;
#pragma unroll
            for (int q = 0; q < 2; q++)
#pragma unroll
                for (int g = 0; g < 4; g++)
                    gxv[q][g] = __ldcs(gxs + (size_t)bb[q] * GDIM + g * HID + cb * 16 + uu[q]);
        }

        // preload W block 0
        uint4 w4[4];
#pragma unroll
        for (int j = 0; j < 4; j++) w4[j] = __ldcg(wsrc + tid + j * 256);

        __syncthreads();   // h staged (also covers W buf reuse from prev step)

        float acc[2][4];
#pragma unroll
        for (int ni = 0; ni < 2; ni++)
#pragma unroll
            for (int e = 0; e < 4; e++) acc[ni][e] = 0.0f;

        for (int blk = 0; blk < 16; blk++) {
            char* wb = sm + RSM_W + (blk & 1) * 16384;
#pragma unroll
            for (int j = 0; j < 4; j++)
                *(uint4*)(wb + (tid + j * 256) * 16) = w4[j];
            if (blk < 15) {
#pragma unroll
                for (int j = 0; j < 4; j++)
                    w4[j] = __ldcg(wsrc + (blk + 1) * 1024 + tid + j * 256);
            }
            __syncthreads();

            const uint32_t wbs = smb + RSM_W + (blk & 1) * 16384;
#pragma unroll
            for (int ks = 0; ks < 4; ks++) {
                uint32_t ah[4], al[4], bh[4], bl[4];
                uint32_t ao = SW128((uint32_t)(
                    (mi * 16 + (lane & 15)) * 128 + ks * 32 + (lane >> 4) * 16));
                LDSM4(ah, wbs + ao);
                LDSM4(al, wbs + 8192 + ao);
                int q = lane >> 3, nf = q >> 1, kl = q & 1;
                uint32_t bo = (uint32_t)(blk * 4096) + SW128((uint32_t)(
                    (nh * 16 + nf * 8 + (lane & 7)) * 128 + ks * 32 + kl * 16));
                LDSM4(bh, smb + RSM_HA + bo);
                LDSM4(bl, smb + RSM_HB + bo);
                MMA_BF16(acc[0], ah, bh[0], bh[1]);
                MMA_BF16(acc[0], ah, bl[0], bl[1]);
                MMA_BF16(acc[0], al, bh[0], bh[1]);
                MMA_BF16(acc[1], ah, bh[2], bh[3]);
                MMA_BF16(acc[1], ah, bl[2], bl[3]);
                MMA_BF16(acc[1], al, bh[2], bh[3]);
            }
        }

        // write G fragments to smem
        {
            int r0 = mi * 16 + (lane >> 2);
            int cc = nh * 16 + (lane & 3) * 2;
#pragma unroll
            for (int ni = 0; ni < 2; ni++) {
                int c = cc + ni * 8;
                Gbuf[r0 * 33 + c]           = acc[ni][0];
                Gbuf[r0 * 33 + c + 1]       = acc[ni][1];
                Gbuf[(r0 + 8) * 33 + c]     = acc[ni][2];
                Gbuf[(r0 + 8) * 33 + c + 1] = acc[ni][3];
            }
        }
        __syncthreads();

        // gate combine + state update + outputs
#pragma unroll
        for (int q = 0; q < 2; q++) {
            int u = uu[q], b = bb[q];
            float iv = hsig (Gbuf[( 0 + u) * 33 + b] + gxv[q][0]);
            float fv = hsig (Gbuf[(16 + u) * 33 + b] + gxv[q][1]);
            float gv = clip1(Gbuf[(32 + u) * 33 + b] + gxv[q][2]);
            float ov = hsig (Gbuf[(48 + u) * 33 + b] + gxv[q][3]);
            float c  = fv * cst[q] + iv * gv;
            cst[q]   = c;
            float h  = ov * clip1(c);
            __nv_bfloat16 hh = __float2bfloat16_rn(h);
            __nv_bfloat16 hl = __float2bfloat16_rn(h - __bfloat162float(hh));
            int gk = cb * 16 + u;
            g_hB[dir][par ^ 1][0][b * 1024 + gk] = hh;
            g_hB[dir][par ^ 1][1][b * 1024 + gk] = hl;
            yout[(size_t)te * BATCH * YW + (size_t)b * YW + dir * HID + gk] = h;
        }

        if (t < T_STEPS - 1) grid_barrier(dir, sense);
    }
}

// ---------------- launch ----------------
extern "C" void kernel_launch(void* const* d_in, const int* in_sizes, int n_in,
                              void* d_out, int out_size)
{
    (void)in_sizes; (void)n_in; (void)out_size;

    const float* x  = (const float*)d_in[0];
    const float* h0 = (const float*)d_in[1];
    const float* c0 = (const float*)d_in[2];
    const float* P[24];
    for (int i = 0; i < 24; i++) P[i] = (const float*)d_in[3 + i];
    // P[(l*2+d)*4 + {0:w_ih, 1:w_hh, 2:b_ih, 3:b_hh}]

    float *gx = nullptr, *yb = nullptr;
    __nv_bfloat16 *whi = nullptr, *wlo = nullptr, *ahi = nullptr, *alo = nullptr;
    uint4* wrec = nullptr;
    cudaGetSymbolAddress((void**)&gx,   g_gx);
    cudaGetSymbolAddress((void**)&yb,   g_ybuf);
    cudaGetSymbolAddress((void**)&whi,  g_whi);
    cudaGetSymbolAddress((void**)&wlo,  g_wlo);
    cudaGetSymbolAddress((void**)&ahi,  g_ahi);
    cudaGetSymbolAddress((void**)&alo,  g_alo);
    cudaGetSymbolAddress((void**)&wrec, g_wrec);
    cudaFuncSetAttribute(rec_kernel, cudaFuncAttributeMaxDynamicSharedMemorySize, REC2_SMEM);
    cudaFuncSetAttribute(gemm_mma,   cudaFuncAttributeMaxDynamicSharedMemorySize, GEMM_SMEM);

    float* y0  = yb;
    float* y1  = yb + (size_t)MROWS * YW;
    float* out = (float*)d_out;

    // bake W_hh smem images (hi/lo, SW128)
    W6 w6;
    for (int i = 0; i < 6; i++) w6.w[i] = P[i * 4 + 1];
    wrec_prep<<<dim3(2048, 6), 256>>>(w6, wrec);

    // w_ih splits
    const size_t woff[6] = {0, 1310720, 2621440, 11010048, 19398656, 27787264};
    const int    wsz [6] = {1310720, 1310720, 8388608, 8388608, 8388608, 8388608};
    const int    wsrc6[6] = {0, 4, 8, 12, 16, 20};
    for (int i = 0; i < 6; i++) {
        int n4 = wsz[i] / 4;
        cvt_split<<<(n4 + 255) / 256, 256>>>((const float4*)P[wsrc6[i]],
                                             whi + woff[i], wlo + woff[i], n4);
    }

    dim3 gg(GDIM / 128, MROWS / 128, 2), gb(256);

    // layer 0 (K = 320)
    cvt_split<<<(MROWS * 320 / 4 + 255) / 256, 256>>>((const float4*)x, ahi, alo, MROWS * 320 / 4);
    gemm_mma<<<gg, gb, GEMM_SMEM>>>(320, ahi, alo,
                                    whi + woff[0], wlo + woff[0], whi + woff[1], wlo + woff[1],
                                    P[2], P[3], P[6], P[7], gx);
    rec_kernel<<<128, 256, REC2_SMEM>>>(wrec, h0, c0, 0, gx, y0);

    // layer 1 (K = 2048)
    cvt_split<<<(MROWS * 2048 / 4 + 255) / 256, 256>>>((const float4*)y0, ahi, alo, MROWS * 2048 / 4);
    gemm_mma<<<gg, gb, GEMM_SMEM>>>(2048, ahi, alo,
                                    whi + woff[2], wlo + woff[2], whi + woff[3], wlo + woff[3],
                                    P[10], P[11], P[14], P[15], gx);
    rec_kernel<<<128, 256, REC2_SMEM>>>(wrec, h0, c0, 1, gx, y1);

    // layer 2 (K = 2048)
    cvt_split<<<(MROWS * 2048 / 4 + 255) / 256, 256>>>((const float4*)y1, ahi, alo, MROWS * 2048 / 4);
    gemm_mma<<<gg, gb, GEMM_SMEM>>>(2048, ahi, alo,
                                    whi + woff[4], wlo + woff[4], whi + woff[5], wlo + woff[5],
                                    P[18], P[19], P[22], P[23], gx);
    rec_kernel<<<128, 256, REC2_SMEM>>>(wrec, h0, c0, 2, gx, out);
}

// round 7
// speedup vs baseline: 3.7867x; 1.1393x over previous
#include <cuda_runtime.h>
#include <cuda_bf16.h>
#include <cstdint>
#include <cstddef>

#define T_STEPS 512
#define BATCH   32
#define HID     1024
#define GDIM    4096
#define MROWS   16384          // T*B
#define YW      2048           // 2*H

typedef unsigned long long ull;

// ---------------- device scratch (no runtime allocation) ----------------
__device__ float g_gx[134217728];        // [2][MROWS][GDIM]  512 MB
__device__ __nv_bfloat16 g_hB[2][2][2][32 * 1024]; // [dir][parity][plane][b*1024+k]
__device__ unsigned g_bar_cnt[2]   = {0, 0};
__device__ unsigned g_bar_phase[2] = {0, 0};
// bf16 split planes for input GEMM
__device__ __nv_bfloat16 g_whi[36700160];   // w_ih hi (all 6)
__device__ __nv_bfloat16 g_wlo[36700160];   // w_ih lo
__device__ __nv_bfloat16 g_ahi[33554432];   // activations hi [16384 x <=2048]
__device__ __nv_bfloat16 g_alo[33554432];   // activations lo
// W_hh baked per-thread fragment streams:
// [ld 6][cb 64][warp 8][kt 32][lane 32] x 32B {ah0..3 | al0..3}
__device__ uint4 g_wrec[6291456];           // 100.66 MB

// ---------------- helpers ----------------
__device__ __forceinline__ uint32_t smem_u32(const void* p) {
    uint32_t a;
    asm("{ .reg .u64 t; cvta.to.shared.u64 t, %1; cvt.u32.u64 %0, t; }" : "=r"(a) : "l"(p));
    return a;
}
#define SW128(o) ((o) ^ (((o) >> 3) & 0x70))

#define MMA_BF16(d, a, b0v, b1v)                                              \
    asm volatile("mma.sync.aligned.m16n8k16.row.col.f32.bf16.bf16.f32 "       \
        "{%0,%1,%2,%3}, {%4,%5,%6,%7}, {%8,%9}, {%0,%1,%2,%3};"               \
        : "+f"((d)[0]), "+f"((d)[1]), "+f"((d)[2]), "+f"((d)[3])              \
        : "r"((a)[0]), "r"((a)[1]), "r"((a)[2]), "r"((a)[3]),                 \
          "r"(b0v), "r"(b1v))

#define LDSM4(r, addr)                                                        \
    asm volatile("ldmatrix.sync.aligned.m8n8.x4.shared.b16 "                  \
        "{%0,%1,%2,%3}, [%4];"                                                \
        : "=r"((r)[0]), "=r"((r)[1]), "=r"((r)[2]), "=r"((r)[3])              \
        : "r"(addr))

__device__ __forceinline__ float hsig(float v)  { return fminf(fmaxf(fmaf(v, 0.2f, 0.5f), 0.0f), 1.0f); }
__device__ __forceinline__ float clip1(float v) { return fminf(fmaxf(v, -1.0f), 1.0f); }

__device__ __forceinline__ void grid_barrier(int dir, unsigned& sense) {
    __syncthreads();
    __threadfence();
    sense ^= 1u;
    if (threadIdx.x == 0) {
        if (atomicAdd(&g_bar_cnt[dir], 1u) == 63u) {
            atomicExch(&g_bar_cnt[dir], 0u);
            __threadfence();
            atomicExch(&g_bar_phase[dir], sense);
        } else {
            while (atomicAdd(&g_bar_phase[dir], 0u) != sense) { __nanosleep(64); }
        }
    }
    __syncthreads();
    __threadfence();
}

// ---------------- fp32 -> bf16 hi/lo split ----------------
__global__ void __launch_bounds__(256)
cvt_split(const float4* __restrict__ src, __nv_bfloat16* __restrict__ hi,
          __nv_bfloat16* __restrict__ lo, int n4)
{
    int i = blockIdx.x * 256 + threadIdx.x;
    if (i >= n4) return;
    float4 v = src[i];
    __nv_bfloat16 h0 = __float2bfloat16_rn(v.x);
    __nv_bfloat16 h1 = __float2bfloat16_rn(v.y);
    __nv_bfloat16 h2 = __float2bfloat16_rn(v.z);
    __nv_bfloat16 h3 = __float2bfloat16_rn(v.w);
    __nv_bfloat16 l0 = __float2bfloat16_rn(v.x - __bfloat162float(h0));
    __nv_bfloat16 l1 = __float2bfloat16_rn(v.y - __bfloat162float(h1));
    __nv_bfloat16 l2 = __float2bfloat16_rn(v.z - __bfloat162float(h2));
    __nv_bfloat16 l3 = __float2bfloat16_rn(v.w - __bfloat162float(h3));
    __nv_bfloat162* H = (__nv_bfloat162*)hi + i * 2;
    __nv_bfloat162* L = (__nv_bfloat162*)lo + i * 2;
    H[0] = __nv_bfloat162(h0, h1); H[1] = __nv_bfloat162(h2, h3);
    L[0] = __nv_bfloat162(l0, l1); L[1] = __nv_bfloat162(l2, l3);
}

// ---------------- W_hh prep: bake per-thread fragment streams ----------------
// Warp layout in rec: wrp -> mi = wrp>>1 (gate/m16 tile), kh = wrp&1 (K half).
// Fragment reg a_j for lane L: row r=(L>>2)+(j&1)*8, kc=(L&3)*2+(j>>1)*8 (bf16x2).
struct W6 { const float* w[6]; };

__global__ void __launch_bounds__(256)
wrec_prep(W6 p, uint4* __restrict__ out)
{
    const int cb = blockIdx.x;
    const int ld = blockIdx.y;
    const float* __restrict__ w = p.w[ld];
    for (int it = 0; it < 32; it++) {
        int v    = it * 256 + threadIdx.x;   // 0..8191
        int wr   = v >> 10;                  // warp 0..7
        int kt   = (v >> 5) & 31;
        int lane = v & 31;
        int mi = wr >> 1, kh = wr & 1;
        unsigned short hi[8], lo[8];
#pragma unroll
        for (int j = 0; j < 4; j++) {
            int r  = (lane >> 2) + (j & 1) * 8;
            int kc = (lane & 3) * 2 + (j >> 1) * 8;
            int row = mi * HID + cb * 16 + r;
            int k   = kh * 512 + kt * 16 + kc;
#pragma unroll
            for (int e = 0; e < 2; e++) {
                float f = w[(size_t)row * HID + k + e];
                __nv_bfloat16 h = __float2bfloat16_rn(f);
                __nv_bfloat16 l = __float2bfloat16_rn(f - __bfloat162float(h));
                hi[j * 2 + e] = *(unsigned short*)&h;
                lo[j * 2 + e] = *(unsigned short*)&l;
            }
        }
        size_t idx = ((((size_t)(ld * 64 + cb) * 8 + wr) * 32 + kt) * 32 + lane) * 2;
        out[idx]     = *(uint4*)hi;
        out[idx + 1] = *(uint4*)lo;
    }
}

// ---------------- tensor-core input-projection GEMM (unchanged, passing) ----------------
#define SMO_AHI 0
#define SMO_ALO 16384
#define SMO_BHI 32768
#define SMO_BLO 49152
#define SMO_BIAS 65536
#define GEMM_SMEM (65536 + 512)

__global__ void __launch_bounds__(256)
gemm_mma(int K,
         const __nv_bfloat16* __restrict__ Ahi, const __nv_bfloat16* __restrict__ Alo,
         const __nv_bfloat16* __restrict__ WhiF, const __nv_bfloat16* __restrict__ WloF,
         const __nv_bfloat16* __restrict__ WhiR, const __nv_bfloat16* __restrict__ WloR,
         const float* __restrict__ bf1, const float* __restrict__ bf2,
         const float* __restrict__ br1, const float* __restrict__ br2,
         float* __restrict__ G)
{
    extern __shared__ char sm[];
    const uint32_t smb = smem_u32(sm);
    const int tid  = threadIdx.x;
    const int wid  = tid >> 5;
    const int lane = tid & 31;
    const int z    = blockIdx.z;

    const __nv_bfloat16* __restrict__ Whi = z ? WhiR : WhiF;
    const __nv_bfloat16* __restrict__ Wlo = z ? WloR : WloF;
    const float* __restrict__ b1 = z ? br1 : bf1;
    const float* __restrict__ b2 = z ? br2 : bf2;
    float* __restrict__ Gz = G + (size_t)z * MROWS * GDIM;

    const int n0 = blockIdx.x * 128;
    const int m0 = blockIdx.y * 128;
    const int wm = (wid >> 2) * 64;
    const int wn = (wid & 3) * 32;

    {
        float* bias = (float*)(sm + SMO_BIAS);
        if (tid < 128) bias[tid] = b1[n0 + tid] + b2[n0 + tid];
    }

    float acc[4][4][4];
#pragma unroll
    for (int mi = 0; mi < 4; mi++)
#pragma unroll
        for (int ni = 0; ni < 4; ni++)
#pragma unroll
            for (int e = 0; e < 4; e++) acc[mi][ni][e] = 0.0f;

    const int nchunk = K >> 6;
    for (int ch = 0; ch < nchunk; ch++) {
        const int kc = ch * 64;
        __syncthreads();
#pragma unroll
        for (int i = 0; i < 4; i++) {
            int v = tid + i * 256;
            int r = v >> 3;
            int c = v & 7;
            uint32_t so = SW128((uint32_t)(r * 128 + c * 16));
            size_t ga = (size_t)(m0 + r) * K + kc + c * 8;
            size_t gb = (size_t)(n0 + r) * K + kc + c * 8;
            *(uint4*)(sm + SMO_AHI + so) = *(const uint4*)(Ahi + ga);
            *(uint4*)(sm + SMO_ALO + so) = *(const uint4*)(Alo + ga);
            *(uint4*)(sm + SMO_BHI + so) = *(const uint4*)(Whi + gb);
            *(uint4*)(sm + SMO_BLO + so) = *(const uint4*)(Wlo + gb);
        }
        __syncthreads();

#pragma unroll
        for (int ks = 0; ks < 4; ks++) {
            uint32_t ah[4][4], al[4][4], bh[2][4], bl[2][4];
#pragma unroll
            for (int mi = 0; mi < 4; mi++) {
                uint32_t off = SW128((uint32_t)(
                    (wm + mi * 16 + (lane & 15)) * 128 + ks * 32 + (lane >> 4) * 16));
                LDSM4(ah[mi], smb + SMO_AHI + off);
                LDSM4(al[mi], smb + SMO_ALO + off);
            }
#pragma unroll
            for (int p = 0; p < 2; p++) {
                int q  = lane >> 3;
                int nf = q >> 1, kl = q & 1;
                uint32_t off = SW128((uint32_t)(
                    (wn + p * 16 + nf * 8 + (lane & 7)) * 128 + ks * 32 + kl * 16));
                LDSM4(bh[p], smb + SMO_BHI + off);
                LDSM4(bl[p], smb + SMO_BLO + off);
            }
#pragma unroll
            for (int mi = 0; mi < 4; mi++) {
#pragma unroll
                for (int ni = 0; ni < 4; ni++) {
                    const int p = ni >> 1, s = (ni & 1) * 2;
                    MMA_BF16(acc[mi][ni], ah[mi], bh[p][s], bh[p][s + 1]);
                    MMA_BF16(acc[mi][ni], ah[mi], bl[p][s], bl[p][s + 1]);
                    MMA_BF16(acc[mi][ni], al[mi], bh[p][s], bh[p][s + 1]);
                }
            }
        }
    }

    const float* bias = (const float*)(sm + SMO_BIAS);
    const int qr = lane >> 2;
    const int qc = (lane & 3) * 2;
#pragma unroll
    for (int mi = 0; mi < 4; mi++) {
#pragma unroll
        for (int ni = 0; ni < 4; ni++) {
            int col = wn + ni * 8 + qc;
            float bx = bias[col], by = bias[col + 1];
            size_t base0 = (size_t)(m0 + wm + mi * 16 + qr) * GDIM + n0 + col;
            size_t base1 = base0 + (size_t)8 * GDIM;
            *(float2*)&Gz[base0] = make_float2(acc[mi][ni][0] + bx, acc[mi][ni][1] + by);
            *(float2*)&Gz[base1] = make_float2(acc[mi][ni][2] + bx, acc[mi][ni][3] + by);
        }
    }
}

// ---------------- persistent tensor-core recurrence (fragment-direct W) ----------------
// 128 CTAs x 256 threads. dir = blockIdx.x>>6; CTA owns 16 units (64 gate rows).
// Warp wrp: mi = wrp>>1 (gate), kh = wrp&1 (K half). Warp = m16 x n32 x K512.
// W streams from L2 in baked fragment order (depth-4 LDG ring, no smem).
#define RSM_HA 0
#define RSM_HB 65536
#define RSM_G  131072
#define REC2_SMEM (131072 + 2*64*33*4)   // 147968 B

__global__ void __launch_bounds__(256)
rec_kernel(const uint4* __restrict__ wrec,
           const float* __restrict__ h0, const float* __restrict__ c0,
           int layer, const float* __restrict__ gx,
           float* __restrict__ yfp,
           __nv_bfloat16* __restrict__ yhi, __nv_bfloat16* __restrict__ ylo)
{
    extern __shared__ char sm[];
    const uint32_t smb = smem_u32(sm);
    float* G0 = (float*)(sm + RSM_G);          // [64][33] partial K-half 0
    float* G1 = G0 + 64 * 33;                  // [64][33] partial K-half 1

    const int tid  = threadIdx.x;
    const int lane = tid & 31;
    const int wrp  = tid >> 5;
    const int mi   = wrp >> 1;
    const int kh   = wrp & 1;
    const int dir  = blockIdx.x >> 6;
    const int cb   = blockIdx.x & 63;
    const int ld   = layer * 2 + dir;
    const float* __restrict__ gxd = gx + (size_t)dir * MROWS * GDIM;
    const uint4* __restrict__ wfrag =
        wrec + (((size_t)(ld * 64 + cb) * 8 + wrp) * 1024 + lane) * 2;
    // per kt advance: 32 lanes * 2 uint4 = 64

    // c-state: 2 (unit,batch) pairs per thread
    float cst[2];
    int uu[2], bb[2];
#pragma unroll
    for (int q = 0; q < 2; q++) {
        int p = q * 256 + tid;
        uu[q] = p >> 5;
        bb[q] = p & 31;
        size_t sidx = (size_t)(2 * layer + dir) * BATCH * HID +
                      (size_t)bb[q] * HID + cb * 16 + uu[q];
        cst[q] = c0[sidx];
        float hv = h0[sidx];
        __nv_bfloat16 hh = __float2bfloat16_rn(hv);
        __nv_bfloat16 hl = __float2bfloat16_rn(hv - __bfloat162float(hh));
        int gk = cb * 16 + uu[q];
        g_hB[dir][0][0][bb[q] * 1024 + gk] = hh;
        g_hB[dir][0][1][bb[q] * 1024 + gk] = hl;
    }

    unsigned sense = 0;
    grid_barrier(dir, sense);

    // ldsm B address components (batches 0-15 and 16-31)
    const int qq = lane >> 3, nf = qq >> 1, kl = qq & 1;
    const uint32_t brow0 = (uint32_t)((nf * 8 + (lane & 7)) * 128 + kl * 16);
    const uint32_t brow1 = brow0 + 16 * 128;

    for (int t = 0; t < T_STEPS; t++) {
        const int par = t & 1;
        const int te  = dir ? (T_STEPS - 1 - t) : t;

        // stage h (2 planes x 64KB) into SW128 k64-blocks
        {
            const uint4* hsrc = (const uint4*)&g_hB[dir][par][0][0];
#pragma unroll
            for (int i = 0; i < 32; i++) {
                int v = tid + i * 256;
                int plane = v >> 12;
                int w = v & 4095;
                int b = w >> 7;
                int kq = w & 127;
                int blk = kq >> 3, cq = kq & 7;
                uint4 d = __ldcg(hsrc + v);
                *(uint4*)(sm + plane * 65536 + blk * 4096 +
                          SW128((uint32_t)(b * 128 + cq * 16))) = d;
            }
        }

        // prefetch gx for combine
        float gxv[2][4];
        {
            const float* gxs = gxd + (size_t)te * BATCH * GDIM;
#pragma unroll
            for (int q = 0; q < 2; q++)
#pragma unroll
                for (int g = 0; g < 4; g++)
                    gxv[q][g] = __ldcs(gxs + (size_t)bb[q] * GDIM + g * HID + cb * 16 + uu[q]);
        }

        // preload W fragment ring (depth 4)
        uint4 pwh[4], pwl[4];
#pragma unroll
        for (int i = 0; i < 4; i++) {
            pwh[i] = __ldcg(wfrag + i * 64);
            pwl[i] = __ldcg(wfrag + i * 64 + 1);
        }

        __syncthreads();   // h staged; also guards G0/G1 reuse from prev step

        float acc[4][4];
#pragma unroll
        for (int s = 0; s < 4; s++)
#pragma unroll
            for (int e = 0; e < 4; e++) acc[s][e] = 0.0f;

#pragma unroll 4
        for (int kt = 0; kt < 32; kt++) {
            const int rs = kt & 3;
            uint32_t ah[4] = {pwh[rs].x, pwh[rs].y, pwh[rs].z, pwh[rs].w};
            uint32_t al[4] = {pwl[rs].x, pwl[rs].y, pwl[rs].z, pwl[rs].w};
            if (kt + 4 < 32) {
                pwh[rs] = __ldcg(wfrag + (kt + 4) * 64);
                pwl[rs] = __ldcg(wfrag + (kt + 4) * 64 + 1);
            }
            const uint32_t blkoff = (uint32_t)((kh * 8 + (kt >> 2)) * 4096);
            const uint32_t cs = (uint32_t)((kt & 3) * 32);
            uint32_t bh0[4], bh1[4], bl0[4], bl1[4];
            LDSM4(bh0, smb + RSM_HA + blkoff + SW128(brow0 + cs));
            LDSM4(bh1, smb + RSM_HA + blkoff + SW128(brow1 + cs));
            LDSM4(bl0, smb + RSM_HB + blkoff + SW128(brow0 + cs));
            LDSM4(bl1, smb + RSM_HB + blkoff + SW128(brow1 + cs));
            MMA_BF16(acc[0], ah, bh0[0], bh0[1]);
            MMA_BF16(acc[0], ah, bl0[0], bl0[1]);
            MMA_BF16(acc[0], al, bh0[0], bh0[1]);
            MMA_BF16(acc[1], ah, bh0[2], bh0[3]);
            MMA_BF16(acc[1], ah, bl0[2], bl0[3]);
            MMA_BF16(acc[1], al, bh0[2], bh0[3]);
            MMA_BF16(acc[2], ah, bh1[0], bh1[1]);
            MMA_BF16(acc[2], ah, bl1[0], bl1[1]);
            MMA_BF16(acc[2], al, bh1[0], bh1[1]);
            MMA_BF16(acc[3], ah, bh1[2], bh1[3]);
            MMA_BF16(acc[3], ah, bl1[2], bl1[3]);
            MMA_BF16(acc[3], al, bh1[2], bh1[3]);
        }

        // write partial G fragments
        {
            float* Gk = kh ? G1 : G0;
            int r0 = mi * 16 + (lane >> 2);
            int cc = (lane & 3) * 2;
#pragma unroll
            for (int s = 0; s < 4; s++) {
                int col = (s >> 1) * 16 + (s & 1) * 8 + cc;
                Gk[r0 * 33 + col]           = acc[s][0];
                Gk[r0 * 33 + col + 1]       = acc[s][1];
                Gk[(r0 + 8) * 33 + col]     = acc[s][2];
                Gk[(r0 + 8) * 33 + col + 1] = acc[s][3];
            }
        }
        __syncthreads();

        // gate combine + state update + outputs
#pragma unroll
        for (int q = 0; q < 2; q++) {
            int u = uu[q], b = bb[q];
            float iv = hsig (G0[( 0 + u) * 33 + b] + G1[( 0 + u) * 33 + b] + gxv[q][0]);
            float fv = hsig (G0[(16 + u) * 33 + b] + G1[(16 + u) * 33 + b] + gxv[q][1]);
            float gv = clip1(G0[(32 + u) * 33 + b] + G1[(32 + u) * 33 + b] + gxv[q][2]);
            float ov = hsig (G0[(48 + u) * 33 + b] + G1[(48 + u) * 33 + b] + gxv[q][3]);
            float c  = fv * cst[q] + iv * gv;
            cst[q]   = c;
            float h  = ov * clip1(c);
            __nv_bfloat16 hh = __float2bfloat16_rn(h);
            __nv_bfloat16 hl = __float2bfloat16_rn(h - __bfloat162float(hh));
            int gk = cb * 16 + u;
            g_hB[dir][par ^ 1][0][b * 1024 + gk] = hh;
            g_hB[dir][par ^ 1][1][b * 1024 + gk] = hl;
            if (yfp) yfp[(size_t)te * BATCH * YW + (size_t)b * YW + dir * HID + gk] = h;
            if (yhi) {
                size_t ai = (size_t)(te * BATCH + b) * YW + dir * HID + gk;
                yhi[ai] = hh;
                ylo[ai] = hl;
            }
        }

        if (t < T_STEPS - 1) grid_barrier(dir, sense);
    }
}

// ---------------- launch ----------------
extern "C" void kernel_launch(void* const* d_in, const int* in_sizes, int n_in,
                              void* d_out, int out_size)
{
    (void)in_sizes; (void)n_in; (void)out_size;

    const float* x  = (const float*)d_in[0];
    const float* h0 = (const float*)d_in[1];
    const float* c0 = (const float*)d_in[2];
    const float* P[24];
    for (int i = 0; i < 24; i++) P[i] = (const float*)d_in[3 + i];
    // P[(l*2+d)*4 + {0:w_ih, 1:w_hh, 2:b_ih, 3:b_hh}]

    float *gx = nullptr;
    __nv_bfloat16 *whi = nullptr, *wlo = nullptr, *ahi = nullptr, *alo = nullptr;
    uint4* wrec = nullptr;
    cudaGetSymbolAddress((void**)&gx,   g_gx);
    cudaGetSymbolAddress((void**)&whi,  g_whi);
    cudaGetSymbolAddress((void**)&wlo,  g_wlo);
    cudaGetSymbolAddress((void**)&ahi,  g_ahi);
    cudaGetSymbolAddress((void**)&alo,  g_alo);
    cudaGetSymbolAddress((void**)&wrec, g_wrec);
    cudaFuncSetAttribute(rec_kernel, cudaFuncAttributeMaxDynamicSharedMemorySize, REC2_SMEM);
    cudaFuncSetAttribute(gemm_mma,   cudaFuncAttributeMaxDynamicSharedMemorySize, GEMM_SMEM);

    float* out = (float*)d_out;

    // bake W_hh fragment streams (hi/lo)
    W6 w6;
    for (int i = 0; i < 6; i++) w6.w[i] = P[i * 4 + 1];
    wrec_prep<<<dim3(64, 6), 256>>>(w6, wrec);

    // w_ih splits
    const size_t woff[6] = {0, 1310720, 2621440, 11010048, 19398656, 27787264};
    const int    wsz [6] = {1310720, 1310720, 8388608, 8388608, 8388608, 8388608};
    const int    wsrc6[6] = {0, 4, 8, 12, 16, 20};
    for (int i = 0; i < 6; i++) {
        int n4 = wsz[i] / 4;
        cvt_split<<<(n4 + 255) / 256, 256>>>((const float4*)P[wsrc6[i]],
                                             whi + woff[i], wlo + woff[i], n4);
    }

    dim3 gg(GDIM / 128, MROWS / 128, 2), gb(256);

    // layer 0 (K = 320); rec writes bf16 activations for layer 1 directly
    cvt_split<<<(MROWS * 320 / 4 + 255) / 256, 256>>>((const float4*)x, ahi, alo, MROWS * 320 / 4);
    gemm_mma<<<gg, gb, GEMM_SMEM>>>(320, ahi, alo,
                                    whi + woff[0], wlo + woff[0], whi + woff[1], wlo + woff[1],
                                    P[2], P[3], P[6], P[7], gx);
    rec_kernel<<<128, 256, REC2_SMEM>>>(wrec, h0, c0, 0, gx, nullptr, ahi, alo);

    // layer 1 (K = 2048)
    gemm_mma<<<gg, gb, GEMM_SMEM>>>(2048, ahi, alo,
                                    whi + woff[2], wlo + woff[2], whi + woff[3], wlo + woff[3],
                                    P[10], P[11], P[14], P[15], gx);
    rec_kernel<<<128, 256, REC2_SMEM>>>(wrec, h0, c0, 1, gx, nullptr, ahi, alo);

    // layer 2 (K = 2048); fp32 output to d_out
    gemm_mma<<<gg, gb, GEMM_SMEM>>>(2048, ahi, alo,
                                    whi + woff[4], wlo + woff[4], whi + woff[5], wlo + woff[5],
                                    P[18], P[19], P[22], P[23], gx);
    rec_kernel<<<128, 256, REC2_SMEM>>>(wrec, h0, c0, 2, gx, out, nullptr, nullptr);
}